// round 10
// baseline (speedup 1.0000x reference)
#include <cuda_runtime.h>
#include <cuda_fp16.h>
#include <cstdint>

// Problem constants
#define IN_F   2048
#define OUT_F  2048
#define NROWS  8192
#define INV_SQRT_D 0.022097086912079610f

// Tiling: 2 CTAs/SM, each BM x BN output tile of BOTH matrices
#define BM 128
#define BN 64
#define KB 64                       // K halfs per stage (one 16KB A sub-tile)
#define NSTG (IN_F / KB)            // 32 stages per tile
#define TILE_HALFS 8192             // 128 rows * 64 halfs (one k-sub-tile of a 128-row block)
#define STAGE_BYTES 32768           // A(16K) + Bk(8K) + Bm(8K)
#define NBUF 3
#define SMEM_TOTAL (NBUF * STAGE_BYTES)   // 98304 per CTA
#define MU_BASE ((size_t)OUT_F * IN_F)
#define NTHREADS 256
#define NCTA 296                    // 2 per SM
#define NTILES ((NROWS / BM) * (OUT_F / BN))   // 64 * 32 = 2048

// Scratch globals: TILED + SWIZZLED layouts (see tiled_off); 32 k-sub-tiles per 128-row block
__device__ __align__(1024) __half Xh[(size_t)NROWS * IN_F];
__device__ __align__(1024) __half Wh[2 * (size_t)OUT_F * IN_F];  // [keys tiles ; mu tiles]

// ---------------------------------------------------------------------------
// PTX helpers
// ---------------------------------------------------------------------------
__device__ __forceinline__ void ldmatrix_x4(uint32_t* r, uint32_t addr) {
    asm volatile("ldmatrix.sync.aligned.m8n8.x4.shared.b16 {%0,%1,%2,%3}, [%4];\n"
                 : "=r"(r[0]), "=r"(r[1]), "=r"(r[2]), "=r"(r[3]) : "r"(addr));
}

__device__ __forceinline__ void mma16816(float* c, const uint32_t* a, const uint32_t* b) {
    asm volatile(
        "mma.sync.aligned.m16n8k16.row.col.f32.f16.f16.f32 "
        "{%0,%1,%2,%3}, {%4,%5,%6,%7}, {%8,%9}, {%0,%1,%2,%3};\n"
        : "+f"(c[0]), "+f"(c[1]), "+f"(c[2]), "+f"(c[3])
        : "r"(a[0]), "r"(a[1]), "r"(a[2]), "r"(a[3]), "r"(b[0]), "r"(b[1]));
}

__device__ __forceinline__ void mbar_init(uint32_t addr, uint32_t count) {
    asm volatile("mbarrier.init.shared.b64 [%0], %1;" :: "r"(addr), "r"(count) : "memory");
}
__device__ __forceinline__ void mbar_expect_tx(uint32_t addr, uint32_t bytes) {
    asm volatile("mbarrier.arrive.expect_tx.shared.b64 _, [%0], %1;"
                 :: "r"(addr), "r"(bytes) : "memory");
}
__device__ __forceinline__ void mbar_arrive(uint32_t addr) {
    asm volatile("mbarrier.arrive.shared.b64 _, [%0];" :: "r"(addr) : "memory");
}
__device__ __forceinline__ void mbar_wait(uint32_t addr, uint32_t parity) {
    asm volatile(
        "{\n\t.reg .pred P;\n\t"
        "WL_%=:\n\t"
        "mbarrier.try_wait.parity.shared.b64 P, [%0], %1, 0x989680;\n\t"
        "@!P bra WL_%=;\n\t}"
        :: "r"(addr), "r"(parity) : "memory");
}
__device__ __forceinline__ void bulk_g2s(uint32_t dst, const void* src,
                                         uint32_t bytes, uint32_t mbar) {
    asm volatile(
        "cp.async.bulk.shared::cluster.global.mbarrier::complete_tx::bytes [%0], [%1], %2, [%3];"
        :: "r"(dst), "l"(src), "r"(bytes), "r"(mbar) : "memory");
}

// ---------------------------------------------------------------------------
// Combined prep kernel: f32 -> f16 into tiled+swizzled layouts (X and W)
// ---------------------------------------------------------------------------
__device__ __forceinline__ size_t tiled_off(int row, int k8) {
    int blk  = row >> 7;
    int rloc = row & 127;
    int kst  = k8 >> 3;               // 16KB sub-tile index (0..31)
    int c    = k8 & 7;
    return (size_t)(blk * 32 + kst) * TILE_HALFS + rloc * 64 + ((c ^ (rloc & 7)) * 8);
}

#define XCHUNKS ((size_t)NROWS * IN_F / 8)
#define XBLOCKS ((unsigned)(XCHUNKS / 256))            // 8192
#define WBLOCKS ((unsigned)(OUT_F * IN_F / 8 / 256))   // 2048

__global__ void prep_all(const float* __restrict__ x,
                         const float* __restrict__ mu,
                         const float* __restrict__ sigma) {
    if (blockIdx.x < XBLOCKS) {
        size_t q = (size_t)blockIdx.x * 256 + threadIdx.x;
        size_t i = q * 8;
        int row = (int)(i >> 11);
        int k8  = (int)((i & 2047) >> 3);
        float4 a = *(const float4*)(x + i);
        float4 b = *(const float4*)(x + i + 4);
        __half2 h0 = __floats2half2_rn(a.x, a.y);
        __half2 h1 = __floats2half2_rn(a.z, a.w);
        __half2 h2 = __floats2half2_rn(b.x, b.y);
        __half2 h3 = __floats2half2_rn(b.z, b.w);
        uint4 p;
        p.x = *(uint32_t*)&h0; p.y = *(uint32_t*)&h1;
        p.z = *(uint32_t*)&h2; p.w = *(uint32_t*)&h3;
        *(uint4*)(Xh + tiled_off(row, k8)) = p;
    } else {
        size_t q = (size_t)(blockIdx.x - XBLOCKS) * 256 + threadIdx.x;
        size_t i = q * 8;
        int row = (int)(i >> 11);
        int k8  = (int)((i & 2047) >> 3);

        float4 m0 = *(const float4*)(mu + i);
        float4 m1 = *(const float4*)(mu + i + 4);
        float4 s0 = *(const float4*)(sigma + i);
        float4 s1 = *(const float4*)(sigma + i + 4);

        float mf[8] = {m0.x, m0.y, m0.z, m0.w, m1.x, m1.y, m1.z, m1.w};
        float sf[8] = {s0.x, s0.y, s0.z, s0.w, s1.x, s1.y, s1.z, s1.w};

        __half kh[8], mh[8];
        #pragma unroll
        for (int j = 0; j < 8; j++) {
            float s  = sf[j];
            float sp = (s > 15.f) ? s : __logf(1.f + __expf(s));
            kh[j] = __float2half_rn(mf[j] * sp);
            mh[j] = __float2half_rn(mf[j]);
        }
        size_t dst = tiled_off(row, k8);
        *(uint4*)(Wh + dst)           = *(uint4*)kh;
        *(uint4*)(Wh + MU_BASE + dst) = *(uint4*)mh;
    }
}

// ---------------------------------------------------------------------------
// Persistent fused GEMM: 296 CTAs (2/SM), each loops tiles cta, cta+296, ...
// Ring-3 of 32KB stages; cross-CTA overlap hides boundaries and epilogues.
// ---------------------------------------------------------------------------
__device__ __forceinline__ void issue_gs(uint32_t smem_u32, uint32_t mbarF_u32,
                                         int gs, int buf, int cta) {
    const int tile = cta + (gs >> 5) * NCTA;
    const int s    = gs & 31;
    const int mblk = tile >> 5;
    const int nblk = tile & 31;
    const __half* gA  = Xh + ((size_t)(mblk * 32 + s)) * TILE_HALFS;
    const __half* gBk = Wh + ((size_t)((nblk >> 1) * 32 + s)) * TILE_HALFS
                           + (size_t)(nblk & 1) * 4096;   // 64-row half (8KB)
    const __half* gBm = gBk + MU_BASE;

    const uint32_t mb  = mbarF_u32 + buf * 8;
    const uint32_t dst = smem_u32 + buf * STAGE_BYTES;
    mbar_expect_tx(mb, STAGE_BYTES);
    bulk_g2s(dst,         gA,  16384, mb);
    bulk_g2s(dst + 16384, gBk,  8192, mb);
    bulk_g2s(dst + 24576, gBm,  8192, mb);
}

__global__ __launch_bounds__(NTHREADS, 2) void gemm_fused(
    const float* __restrict__ gate,
    float* __restrict__ outFinal,
    float* __restrict__ outScores,
    float* __restrict__ outMasked)
{
    extern __shared__ char smem[];
    __shared__ __align__(8) uint64_t mbarF[NBUF];
    __shared__ __align__(8) uint64_t mbarE[NBUF];

    const uint32_t smem_u32  = (uint32_t)__cvta_generic_to_shared(smem);
    const uint32_t mbarF_u32 = (uint32_t)__cvta_generic_to_shared(mbarF);
    const uint32_t mbarE_u32 = (uint32_t)__cvta_generic_to_shared(mbarE);

    const int tid    = threadIdx.x;
    const int lane   = tid & 31;
    const int wid    = tid >> 5;
    const int warp_m = wid >> 2;      // 0..1 -> 64 rows each
    const int warp_n = wid & 3;       // 0..3 -> 16 cols each
    const int cta    = blockIdx.x;

    const int my_tiles = (NTILES - 1 - cta) / NCTA + 1;
    const int total_gs = my_tiles * NSTG;

    if (tid == 0) {
        #pragma unroll
        for (int b = 0; b < NBUF; b++) {
            mbar_init(mbarF_u32 + b * 8, 1);
            mbar_init(mbarE_u32 + b * 8, 8);   // one arrive per warp
        }
    }
    __syncthreads();

    if (tid == 0) {
        issue_gs(smem_u32, mbarF_u32, 0, 0, cta);
        issue_gs(smem_u32, mbarF_u32, 1, 1, cta);
        issue_gs(smem_u32, mbarF_u32, 2, 2, cta);
    }

    float acck[4][2][4], accm[4][2][4];
    #pragma unroll
    for (int mt = 0; mt < 4; mt++)
        #pragma unroll
        for (int nt = 0; nt < 2; nt++)
            #pragma unroll
            for (int q = 0; q < 4; q++) { acck[mt][nt][q] = 0.f; accm[mt][nt][q] = 0.f; }

    const int a_row = lane & 15;
    const int a_sel = lane >> 4;
    const int b_row = (lane & 7) + ((lane & 16) >> 1);
    const int b_sel = (lane & 8) ? 1 : 0;

    int cbuf = 0, cph = 0;   // consumer cursor: buffer + phase (round parity)

    for (int gs = 0; gs < total_gs; gs++) {
        // Consumer: wait for this stage's data.
        mbar_wait(mbarF_u32 + cbuf * 8, cph);

        const uint32_t sA  = smem_u32 + cbuf * STAGE_BYTES;
        const uint32_t sBk = sA + 16384;
        const uint32_t sBm = sA + 24576;

        #pragma unroll
        for (int ks = 0; ks < 4; ks++) {
            uint32_t af[4][4];
            #pragma unroll
            for (int mt = 0; mt < 4; mt++) {
                int row = warp_m * 64 + mt * 16 + a_row;
                int ch  = (ks * 2 + a_sel) ^ (row & 7);
                ldmatrix_x4(af[mt], sA + row * 128 + ch * 16);
            }
            uint32_t bk[2][2], bmu[2][2];
            {
                int row = warp_n * 16 + b_row;
                int ch  = (ks * 2 + b_sel) ^ (row & 7);
                uint32_t r[4];
                ldmatrix_x4(r, sBk + row * 128 + ch * 16);
                bk[0][0] = r[0]; bk[0][1] = r[1];
                bk[1][0] = r[2]; bk[1][1] = r[3];
                uint32_t t[4];
                ldmatrix_x4(t, sBm + row * 128 + ch * 16);
                bmu[0][0] = t[0]; bmu[0][1] = t[1];
                bmu[1][0] = t[2]; bmu[1][1] = t[3];
            }
            #pragma unroll
            for (int mt = 0; mt < 4; mt++) {
                #pragma unroll
                for (int nt = 0; nt < 2; nt++) {
                    mma16816(acck[mt][nt], af[mt], bk[nt]);
                    mma16816(accm[mt][nt], af[mt], bmu[nt]);
                }
            }
        }

        // Warp done reading buffer cbuf.
        if (lane == 0) mbar_arrive(mbarE_u32 + cbuf * 8);

        // Producer: refill buffer cbuf with stage gs+3 (same buffer in ring-3).
        if (tid == 0 && gs + 3 < total_gs) {
            mbar_wait(mbarE_u32 + cbuf * 8, cph);
            issue_gs(smem_u32, mbarF_u32, gs + 3, cbuf, cta);
        }

        // Tile finished: fused epilogue (sibling CTA covers the tensor pipe).
        if ((gs & 31) == 31) {
            const int tile = cta + (gs >> 5) * NCTA;
            const int bm = (tile >> 5) * BM;
            const int bn = (tile & 31) * BN;

            #pragma unroll
            for (int mt = 0; mt < 4; mt++) {
                int r0 = bm + warp_m * 64 + mt * 16 + (lane >> 2);
                #pragma unroll
                for (int nt = 0; nt < 2; nt++) {
                    int c = bn + warp_n * 16 + nt * 8 + (lane & 3) * 2;
                    float2 g = __ldg((const float2*)(gate + c));

                    float s0 = acck[mt][nt][0] * INV_SQRT_D;
                    float s1 = acck[mt][nt][1] * INV_SQRT_D;
                    float m0 = accm[mt][nt][0] * fmaxf(s0 - g.x, 0.f);
                    float m1 = accm[mt][nt][1] * fmaxf(s1 - g.y, 0.f);
                    size_t o0 = (size_t)r0 * OUT_F + c;
                    *(float2*)(outScores + o0) = make_float2(s0, s1);
                    *(float2*)(outFinal  + o0) = make_float2(m0, m1);
                    *(float2*)(outMasked + o0) = make_float2(m0, m1);

                    float s2 = acck[mt][nt][2] * INV_SQRT_D;
                    float s3 = acck[mt][nt][3] * INV_SQRT_D;
                    float m2 = accm[mt][nt][2] * fmaxf(s2 - g.x, 0.f);
                    float m3 = accm[mt][nt][3] * fmaxf(s3 - g.y, 0.f);
                    size_t o1 = (size_t)(r0 + 8) * OUT_F + c;
                    *(float2*)(outScores + o1) = make_float2(s2, s3);
                    *(float2*)(outFinal  + o1) = make_float2(m2, m3);
                    *(float2*)(outMasked + o1) = make_float2(m2, m3);

                    #pragma unroll
                    for (int q = 0; q < 4; q++) { acck[mt][nt][q] = 0.f; accm[mt][nt][q] = 0.f; }
                }
            }
        }

        // Advance ring cursor.
        if (++cbuf == NBUF) { cbuf = 0; cph ^= 1; }
    }
}

// ---------------------------------------------------------------------------
// Launch
// ---------------------------------------------------------------------------
extern "C" void kernel_launch(void* const* d_in, const int* in_sizes, int n_in,
                              void* d_out, int out_size) {
    const float* x     = (const float*)d_in[0];
    const float* mu    = (const float*)d_in[1];
    const float* sigma = (const float*)d_in[2];
    const float* gate  = (const float*)d_in[3];

    float* out  = (float*)d_out;
    float* out0 = out;                               // final_output
    float* out1 = out + (size_t)NROWS * OUT_F;       // scores
    float* out2 = out + 2 * (size_t)NROWS * OUT_F;   // masked_output

    prep_all<<<XBLOCKS + WBLOCKS, 256>>>(x, mu, sigma);

    cudaFuncSetAttribute(gemm_fused, cudaFuncAttributeMaxDynamicSharedMemorySize, SMEM_TOTAL);
    gemm_fused<<<NCTA, NTHREADS, SMEM_TOTAL>>>(gate, out0, out1, out2);
}

// round 11
// speedup vs baseline: 1.1010x; 1.1010x over previous
#include <cuda_runtime.h>
#include <cuda_fp16.h>
#include <cstdint>

// Problem constants
#define IN_F   2048
#define OUT_F  2048
#define NROWS  8192
#define INV_SQRT_D 0.022097086912079610f

// Tiling
#define BM 128
#define BN 128
#define KB 128                      // K halfs per stage (two 16KB sub-tiles)
#define NSTG (IN_F / KB)            // 16 stages per tile
#define TILE_HALFS 8192             // 128 rows * 64 halfs (one k-sub-tile)
#define SUB_BYTES 16384
#define STAGE_BYTES 98304           // A(32K) + Bk(32K) + Bm(32K)
#define NBUF 2
#define SMEM_TOTAL (NBUF * STAGE_BYTES)   // 196608
#define MU_BASE ((size_t)OUT_F * IN_F)
#define NTHREADS 256
#define NSM 148
#define NTILES ((NROWS / BM) * (OUT_F / BN))   // 64 * 16 = 1024

// Scratch globals: TILED + SWIZZLED layouts (see tiled_off); 32 k-sub-tiles/block
__device__ __align__(1024) __half Xh[(size_t)NROWS * IN_F];
__device__ __align__(1024) __half Wh[2 * (size_t)OUT_F * IN_F];  // [keys tiles ; mu tiles]

// ---------------------------------------------------------------------------
// PTX helpers
// ---------------------------------------------------------------------------
__device__ __forceinline__ void ldmatrix_x4(uint32_t* r, uint32_t addr) {
    asm volatile("ldmatrix.sync.aligned.m8n8.x4.shared.b16 {%0,%1,%2,%3}, [%4];\n"
                 : "=r"(r[0]), "=r"(r[1]), "=r"(r[2]), "=r"(r[3]) : "r"(addr));
}

__device__ __forceinline__ void mma16816(float* c, const uint32_t* a, const uint32_t* b) {
    asm volatile(
        "mma.sync.aligned.m16n8k16.row.col.f32.f16.f16.f32 "
        "{%0,%1,%2,%3}, {%4,%5,%6,%7}, {%8,%9}, {%0,%1,%2,%3};\n"
        : "+f"(c[0]), "+f"(c[1]), "+f"(c[2]), "+f"(c[3])
        : "r"(a[0]), "r"(a[1]), "r"(a[2]), "r"(a[3]), "r"(b[0]), "r"(b[1]));
}

__device__ __forceinline__ void mbar_init(uint32_t addr, uint32_t count) {
    asm volatile("mbarrier.init.shared.b64 [%0], %1;" :: "r"(addr), "r"(count) : "memory");
}
__device__ __forceinline__ void mbar_expect_tx(uint32_t addr, uint32_t bytes) {
    asm volatile("mbarrier.arrive.expect_tx.shared.b64 _, [%0], %1;"
                 :: "r"(addr), "r"(bytes) : "memory");
}
__device__ __forceinline__ void mbar_arrive(uint32_t addr) {
    asm volatile("mbarrier.arrive.shared.b64 _, [%0];" :: "r"(addr) : "memory");
}
__device__ __forceinline__ void mbar_wait(uint32_t addr, uint32_t parity) {
    asm volatile(
        "{\n\t.reg .pred P;\n\t"
        "WL_%=:\n\t"
        "mbarrier.try_wait.parity.shared.b64 P, [%0], %1, 0x989680;\n\t"
        "@!P bra WL_%=;\n\t}"
        :: "r"(addr), "r"(parity) : "memory");
}
__device__ __forceinline__ void bulk_g2s(uint32_t dst, const void* src,
                                         uint32_t bytes, uint32_t mbar) {
    asm volatile(
        "cp.async.bulk.shared::cluster.global.mbarrier::complete_tx::bytes [%0], [%1], %2, [%3];"
        :: "r"(dst), "l"(src), "r"(bytes), "r"(mbar) : "memory");
}

// ---------------------------------------------------------------------------
// Combined prep kernel: f32 -> f16 into tiled+swizzled layouts (X and W)
// ---------------------------------------------------------------------------
__device__ __forceinline__ size_t tiled_off(int row, int k8) {
    int blk  = row >> 7;
    int rloc = row & 127;
    int kst  = k8 >> 3;               // 16KB sub-tile index (0..31)
    int c    = k8 & 7;
    return (size_t)(blk * 32 + kst) * TILE_HALFS + rloc * 64 + ((c ^ (rloc & 7)) * 8);
}

#define XCHUNKS ((size_t)NROWS * IN_F / 8)
#define XBLOCKS ((unsigned)(XCHUNKS / 256))            // 8192
#define WBLOCKS ((unsigned)(OUT_F * IN_F / 8 / 256))   // 2048

__global__ void prep_all(const float* __restrict__ x,
                         const float* __restrict__ mu,
                         const float* __restrict__ sigma) {
    if (blockIdx.x < XBLOCKS) {
        size_t q = (size_t)blockIdx.x * 256 + threadIdx.x;
        size_t i = q * 8;
        int row = (int)(i >> 11);
        int k8  = (int)((i & 2047) >> 3);
        float4 a = *(const float4*)(x + i);
        float4 b = *(const float4*)(x + i + 4);
        __half2 h0 = __floats2half2_rn(a.x, a.y);
        __half2 h1 = __floats2half2_rn(a.z, a.w);
        __half2 h2 = __floats2half2_rn(b.x, b.y);
        __half2 h3 = __floats2half2_rn(b.z, b.w);
        uint4 p;
        p.x = *(uint32_t*)&h0; p.y = *(uint32_t*)&h1;
        p.z = *(uint32_t*)&h2; p.w = *(uint32_t*)&h3;
        *(uint4*)(Xh + tiled_off(row, k8)) = p;
    } else {
        size_t q = (size_t)(blockIdx.x - XBLOCKS) * 256 + threadIdx.x;
        size_t i = q * 8;
        int row = (int)(i >> 11);
        int k8  = (int)((i & 2047) >> 3);

        float4 m0 = *(const float4*)(mu + i);
        float4 m1 = *(const float4*)(mu + i + 4);
        float4 s0 = *(const float4*)(sigma + i);
        float4 s1 = *(const float4*)(sigma + i + 4);

        float mf[8] = {m0.x, m0.y, m0.z, m0.w, m1.x, m1.y, m1.z, m1.w};
        float sf[8] = {s0.x, s0.y, s0.z, s0.w, s1.x, s1.y, s1.z, s1.w};

        __half kh[8], mh[8];
        #pragma unroll
        for (int j = 0; j < 8; j++) {
            float s  = sf[j];
            float sp = (s > 15.f) ? s : __logf(1.f + __expf(s));
            kh[j] = __float2half_rn(mf[j] * sp);
            mh[j] = __float2half_rn(mf[j]);
        }
        size_t dst = tiled_off(row, k8);
        *(uint4*)(Wh + dst)           = *(uint4*)kh;
        *(uint4*)(Wh + MU_BASE + dst) = *(uint4*)mh;
    }
}

// ---------------------------------------------------------------------------
// Persistent fused GEMM: 148 CTAs, ring-2 of 96KB stages; hoisted next-stage
// wait + early buffer release hide stage-boundary latency.
// ---------------------------------------------------------------------------
__device__ __forceinline__ void issue_gs(uint32_t smem_u32, uint32_t mbarF_u32,
                                         int gs, int cta) {
    const int tile = cta + (gs >> 4) * NSM;
    const int s    = gs & 15;
    const int mblk = tile >> 4;
    const int nblk = tile & 15;
    const __half* gA  = Xh + ((size_t)mblk * 32 + 2 * s) * TILE_HALFS;
    const __half* gBk = Wh + ((size_t)nblk * 32 + 2 * s) * TILE_HALFS;
    const __half* gBm = gBk + MU_BASE;

    const int b = gs & 1;
    const uint32_t mb  = mbarF_u32 + b * 8;
    const uint32_t dst = smem_u32 + b * STAGE_BYTES;
    mbar_expect_tx(mb, STAGE_BYTES);
    bulk_g2s(dst,         gA,  2 * SUB_BYTES, mb);
    bulk_g2s(dst + 32768, gBk, 2 * SUB_BYTES, mb);
    bulk_g2s(dst + 65536, gBm, 2 * SUB_BYTES, mb);
}

__global__ __launch_bounds__(NTHREADS, 1) void gemm_fused(
    const float* __restrict__ gate,
    float* __restrict__ outFinal,
    float* __restrict__ outScores,
    float* __restrict__ outMasked)
{
    extern __shared__ char smem[];
    __shared__ __align__(8) uint64_t mbarF[NBUF];
    __shared__ __align__(8) uint64_t mbarE[NBUF];

    const uint32_t smem_u32  = (uint32_t)__cvta_generic_to_shared(smem);
    const uint32_t mbarF_u32 = (uint32_t)__cvta_generic_to_shared(mbarF);
    const uint32_t mbarE_u32 = (uint32_t)__cvta_generic_to_shared(mbarE);

    const int tid    = threadIdx.x;
    const int lane   = tid & 31;
    const int wid    = tid >> 5;
    const int warp_m = wid >> 2;      // 0..1 -> 64 rows each
    const int warp_n = wid & 3;       // 0..3 -> 32 cols each
    const int cta    = blockIdx.x;

    const int my_tiles = (NTILES - 1 - cta) / NSM + 1;
    const int total_gs = my_tiles * NSTG;

    if (tid == 0) {
        #pragma unroll
        for (int b = 0; b < NBUF; b++) {
            mbar_init(mbarF_u32 + b * 8, 1);
            mbar_init(mbarE_u32 + b * 8, 8);   // one arrive per warp
        }
    }
    __syncthreads();

    if (tid == 0) {
        issue_gs(smem_u32, mbarF_u32, 0, cta);
        issue_gs(smem_u32, mbarF_u32, 1, cta);
    }

    float acck[4][4][4], accm[4][4][4];
    #pragma unroll
    for (int mt = 0; mt < 4; mt++)
        #pragma unroll
        for (int nt = 0; nt < 4; nt++)
            #pragma unroll
            for (int q = 0; q < 4; q++) { acck[mt][nt][q] = 0.f; accm[mt][nt][q] = 0.f; }

    const int a_row = lane & 15;
    const int a_sel = lane >> 4;
    const int b_row = (lane & 7) + ((lane & 16) >> 1);
    const int b_sel = (lane & 8) ? 1 : 0;

    // Wait for stage 0 once; subsequent waits are hoisted into MMA shadows.
    mbar_wait(mbarF_u32, 0);

    for (int gs = 0; gs < total_gs; gs++) {
        const int b = gs & 1;

        const uint32_t sA  = smem_u32 + b * STAGE_BYTES;
        const uint32_t sBk = sA + 32768;
        const uint32_t sBm = sA + 65536;

        #pragma unroll
        for (int ks = 0; ks < 8; ks++) {
            const int sub = (ks >> 2) * SUB_BYTES;
            const int kk  = ks & 3;
            uint32_t af[4][4];
            #pragma unroll
            for (int mt = 0; mt < 4; mt++) {
                int row = warp_m * 64 + mt * 16 + a_row;
                int ch  = (kk * 2 + a_sel) ^ (row & 7);
                ldmatrix_x4(af[mt], sA + sub + row * 128 + ch * 16);
            }
            uint32_t bk[4][2], bmu[4][2];
            #pragma unroll
            for (int bt = 0; bt < 2; bt++) {
                int row = warp_n * 32 + bt * 16 + b_row;
                int ch  = (kk * 2 + b_sel) ^ (row & 7);
                uint32_t r[4];
                ldmatrix_x4(r, sBk + sub + row * 128 + ch * 16);
                bk[2*bt  ][0] = r[0]; bk[2*bt  ][1] = r[1];
                bk[2*bt+1][0] = r[2]; bk[2*bt+1][1] = r[3];
                uint32_t t[4];
                ldmatrix_x4(t, sBm + sub + row * 128 + ch * 16);
                bmu[2*bt  ][0] = t[0]; bmu[2*bt  ][1] = t[1];
                bmu[2*bt+1][0] = t[2]; bmu[2*bt+1][1] = t[3];
            }

            if (ks == 7) {
                // Early release: all smem reads of this stage are issued.
                if (lane == 0) mbar_arrive(mbarE_u32 + b * 8);
                // Hoisted wait for next stage: overlaps the final MMA batch.
                if (gs + 1 < total_gs) {
                    const int n = gs + 1;
                    mbar_wait(mbarF_u32 + (n & 1) * 8, (n >> 1) & 1);
                }
            }

            #pragma unroll
            for (int mt = 0; mt < 4; mt++) {
                #pragma unroll
                for (int nt = 0; nt < 4; nt++) {
                    mma16816(acck[mt][nt], af[mt], bk[nt]);
                    mma16816(accm[mt][nt], af[mt], bmu[nt]);
                }
            }
        }

        // Producer: refill buffer b with global stage gs+2 (may be next tile).
        if (tid == 0 && gs + 2 < total_gs) {
            const int t = gs + 2;
            mbar_wait(mbarE_u32 + b * 8, (((t >> 1) & 1) ^ 1));
            issue_gs(smem_u32, mbarF_u32, t, cta);
        }

        // Tile finished: fused epilogue (overlaps next tile's loads).
        if ((gs & 15) == 15) {
            const int tile = cta + (gs >> 4) * NSM;
            const int bm = (tile >> 4) * BM;
            const int bn = (tile & 15) * BN;

            #pragma unroll
            for (int mt = 0; mt < 4; mt++) {
                int r0 = bm + warp_m * 64 + mt * 16 + (lane >> 2);
                #pragma unroll
                for (int nt = 0; nt < 4; nt++) {
                    int c = bn + warp_n * 32 + nt * 8 + (lane & 3) * 2;
                    float2 g = __ldg((const float2*)(gate + c));

                    float s0 = acck[mt][nt][0] * INV_SQRT_D;
                    float s1 = acck[mt][nt][1] * INV_SQRT_D;
                    float m0 = accm[mt][nt][0] * fmaxf(s0 - g.x, 0.f);
                    float m1 = accm[mt][nt][1] * fmaxf(s1 - g.y, 0.f);
                    size_t o0 = (size_t)r0 * OUT_F + c;
                    *(float2*)(outScores + o0) = make_float2(s0, s1);
                    *(float2*)(outFinal  + o0) = make_float2(m0, m1);
                    *(float2*)(outMasked + o0) = make_float2(m0, m1);

                    float s2 = acck[mt][nt][2] * INV_SQRT_D;
                    float s3 = acck[mt][nt][3] * INV_SQRT_D;
                    float m2 = accm[mt][nt][2] * fmaxf(s2 - g.x, 0.f);
                    float m3 = accm[mt][nt][3] * fmaxf(s3 - g.y, 0.f);
                    size_t o1 = (size_t)(r0 + 8) * OUT_F + c;
                    *(float2*)(outScores + o1) = make_float2(s2, s3);
                    *(float2*)(outFinal  + o1) = make_float2(m2, m3);
                    *(float2*)(outMasked + o1) = make_float2(m2, m3);

                    #pragma unroll
                    for (int q = 0; q < 4; q++) { acck[mt][nt][q] = 0.f; accm[mt][nt][q] = 0.f; }
                }
            }
        }
    }
}

// ---------------------------------------------------------------------------
// Launch
// ---------------------------------------------------------------------------
extern "C" void kernel_launch(void* const* d_in, const int* in_sizes, int n_in,
                              void* d_out, int out_size) {
    const float* x     = (const float*)d_in[0];
    const float* mu    = (const float*)d_in[1];
    const float* sigma = (const float*)d_in[2];
    const float* gate  = (const float*)d_in[3];

    float* out  = (float*)d_out;
    float* out0 = out;                               // final_output
    float* out1 = out + (size_t)NROWS * OUT_F;       // scores
    float* out2 = out + 2 * (size_t)NROWS * OUT_F;   // masked_output

    prep_all<<<XBLOCKS + WBLOCKS, 256>>>(x, mu, sigma);

    cudaFuncSetAttribute(gemm_fused, cudaFuncAttributeMaxDynamicSharedMemorySize, SMEM_TOTAL);
    gemm_fused<<<NSM, NTHREADS, SMEM_TOTAL>>>(gate, out0, out1, out2);
}

// round 12
// speedup vs baseline: 1.1047x; 1.0033x over previous
#include <cuda_runtime.h>
#include <cuda_fp16.h>
#include <cstdint>

// Problem constants
#define IN_F   2048
#define OUT_F  2048
#define NROWS  8192
#define INV_SQRT_D 0.022097086912079610f

// Tiling
#define BM 128
#define BN 128
#define KB 128                      // K halfs per stage (two 16KB sub-tiles)
#define NSTG (IN_F / KB)            // 16 stages per tile
#define TILE_HALFS 8192             // 128 rows * 64 halfs (one k-sub-tile)
#define SUB_BYTES 16384
#define STAGE_BYTES 98304           // A(32K) + Bk(32K) + Bm(32K)
#define NBUF 2
#define SMEM_TOTAL (NBUF * STAGE_BYTES)   // 196608
#define MU_BASE ((size_t)OUT_F * IN_F)
#define NTHREADS 256
#define NSM 148
#define NTILES ((NROWS / BM) * (OUT_F / BN))   // 64 * 16 = 1024

// Scratch globals: TILED + SWIZZLED layouts (see tiled_off); 32 k-sub-tiles/block
__device__ __align__(1024) __half Xh[(size_t)NROWS * IN_F];
__device__ __align__(1024) __half Wh[2 * (size_t)OUT_F * IN_F];  // [keys tiles ; mu tiles]

// ---------------------------------------------------------------------------
// PTX helpers
// ---------------------------------------------------------------------------
__device__ __forceinline__ void ldmatrix_x4(uint32_t* r, uint32_t addr) {
    asm volatile("ldmatrix.sync.aligned.m8n8.x4.shared.b16 {%0,%1,%2,%3}, [%4];\n"
                 : "=r"(r[0]), "=r"(r[1]), "=r"(r[2]), "=r"(r[3]) : "r"(addr));
}

__device__ __forceinline__ void mma16816(float* c, const uint32_t* a, const uint32_t* b) {
    asm volatile(
        "mma.sync.aligned.m16n8k16.row.col.f32.f16.f16.f32 "
        "{%0,%1,%2,%3}, {%4,%5,%6,%7}, {%8,%9}, {%0,%1,%2,%3};\n"
        : "+f"(c[0]), "+f"(c[1]), "+f"(c[2]), "+f"(c[3])
        : "r"(a[0]), "r"(a[1]), "r"(a[2]), "r"(a[3]), "r"(b[0]), "r"(b[1]));
}

__device__ __forceinline__ void mbar_init(uint32_t addr, uint32_t count) {
    asm volatile("mbarrier.init.shared.b64 [%0], %1;" :: "r"(addr), "r"(count) : "memory");
}
__device__ __forceinline__ void mbar_expect_tx(uint32_t addr, uint32_t bytes) {
    asm volatile("mbarrier.arrive.expect_tx.shared.b64 _, [%0], %1;"
                 :: "r"(addr), "r"(bytes) : "memory");
}
__device__ __forceinline__ void mbar_arrive(uint32_t addr) {
    asm volatile("mbarrier.arrive.shared.b64 _, [%0];" :: "r"(addr) : "memory");
}
__device__ __forceinline__ void mbar_wait(uint32_t addr, uint32_t parity) {
    asm volatile(
        "{\n\t.reg .pred P;\n\t"
        "WL_%=:\n\t"
        "mbarrier.try_wait.parity.shared.b64 P, [%0], %1, 0x989680;\n\t"
        "@!P bra WL_%=;\n\t}"
        :: "r"(addr), "r"(parity) : "memory");
}
__device__ __forceinline__ void bulk_g2s(uint32_t dst, const void* src,
                                         uint32_t bytes, uint32_t mbar) {
    asm volatile(
        "cp.async.bulk.shared::cluster.global.mbarrier::complete_tx::bytes [%0], [%1], %2, [%3];"
        :: "r"(dst), "l"(src), "r"(bytes), "r"(mbar) : "memory");
}

// ---------------------------------------------------------------------------
// Combined prep kernel: f32 -> f16 into tiled+swizzled layouts (X and W)
// ---------------------------------------------------------------------------
__device__ __forceinline__ size_t tiled_off(int row, int k8) {
    int blk  = row >> 7;
    int rloc = row & 127;
    int kst  = k8 >> 3;               // 16KB sub-tile index (0..31)
    int c    = k8 & 7;
    return (size_t)(blk * 32 + kst) * TILE_HALFS + rloc * 64 + ((c ^ (rloc & 7)) * 8);
}

#define XCHUNKS ((size_t)NROWS * IN_F / 8)
#define XBLOCKS ((unsigned)(XCHUNKS / 256))            // 8192
#define WBLOCKS ((unsigned)(OUT_F * IN_F / 8 / 256))   // 2048

__global__ void prep_all(const float* __restrict__ x,
                         const float* __restrict__ mu,
                         const float* __restrict__ sigma) {
    if (blockIdx.x < XBLOCKS) {
        size_t q = (size_t)blockIdx.x * 256 + threadIdx.x;
        size_t i = q * 8;
        int row = (int)(i >> 11);
        int k8  = (int)((i & 2047) >> 3);
        float4 a = *(const float4*)(x + i);
        float4 b = *(const float4*)(x + i + 4);
        __half2 h0 = __floats2half2_rn(a.x, a.y);
        __half2 h1 = __floats2half2_rn(a.z, a.w);
        __half2 h2 = __floats2half2_rn(b.x, b.y);
        __half2 h3 = __floats2half2_rn(b.z, b.w);
        uint4 p;
        p.x = *(uint32_t*)&h0; p.y = *(uint32_t*)&h1;
        p.z = *(uint32_t*)&h2; p.w = *(uint32_t*)&h3;
        *(uint4*)(Xh + tiled_off(row, k8)) = p;
    } else {
        size_t q = (size_t)(blockIdx.x - XBLOCKS) * 256 + threadIdx.x;
        size_t i = q * 8;
        int row = (int)(i >> 11);
        int k8  = (int)((i & 2047) >> 3);

        float4 m0 = *(const float4*)(mu + i);
        float4 m1 = *(const float4*)(mu + i + 4);
        float4 s0 = *(const float4*)(sigma + i);
        float4 s1 = *(const float4*)(sigma + i + 4);

        float mf[8] = {m0.x, m0.y, m0.z, m0.w, m1.x, m1.y, m1.z, m1.w};
        float sf[8] = {s0.x, s0.y, s0.z, s0.w, s1.x, s1.y, s1.z, s1.w};

        __half kh[8], mh[8];
        #pragma unroll
        for (int j = 0; j < 8; j++) {
            float s  = sf[j];
            float sp = (s > 15.f) ? s : __logf(1.f + __expf(s));
            kh[j] = __float2half_rn(mf[j] * sp);
            mh[j] = __float2half_rn(mf[j]);
        }
        size_t dst = tiled_off(row, k8);
        *(uint4*)(Wh + dst)           = *(uint4*)kh;
        *(uint4*)(Wh + MU_BASE + dst) = *(uint4*)mh;
    }
}

// ---------------------------------------------------------------------------
// Persistent fused GEMM: 148 CTAs, ring-2 of 96KB stages; hoisted next-stage
// wait + early release + ANTI-PHASED ks order between SMSP warp pairs.
// ---------------------------------------------------------------------------
__device__ __forceinline__ void issue_gs(uint32_t smem_u32, uint32_t mbarF_u32,
                                         int gs, int cta) {
    const int tile = cta + (gs >> 4) * NSM;
    const int s    = gs & 15;
    const int mblk = tile >> 4;
    const int nblk = tile & 15;
    const __half* gA  = Xh + ((size_t)mblk * 32 + 2 * s) * TILE_HALFS;
    const __half* gBk = Wh + ((size_t)nblk * 32 + 2 * s) * TILE_HALFS;
    const __half* gBm = gBk + MU_BASE;

    const int b = gs & 1;
    const uint32_t mb  = mbarF_u32 + b * 8;
    const uint32_t dst = smem_u32 + b * STAGE_BYTES;
    mbar_expect_tx(mb, STAGE_BYTES);
    bulk_g2s(dst,         gA,  2 * SUB_BYTES, mb);
    bulk_g2s(dst + 32768, gBk, 2 * SUB_BYTES, mb);
    bulk_g2s(dst + 65536, gBm, 2 * SUB_BYTES, mb);
}

__global__ __launch_bounds__(NTHREADS, 1) void gemm_fused(
    const float* __restrict__ gate,
    float* __restrict__ outFinal,
    float* __restrict__ outScores,
    float* __restrict__ outMasked)
{
    extern __shared__ char smem[];
    __shared__ __align__(8) uint64_t mbarF[NBUF];
    __shared__ __align__(8) uint64_t mbarE[NBUF];

    const uint32_t smem_u32  = (uint32_t)__cvta_generic_to_shared(smem);
    const uint32_t mbarF_u32 = (uint32_t)__cvta_generic_to_shared(mbarF);
    const uint32_t mbarE_u32 = (uint32_t)__cvta_generic_to_shared(mbarE);

    const int tid    = threadIdx.x;
    const int lane   = tid & 31;
    const int wid    = tid >> 5;
    const int warp_m = wid >> 2;      // 0..1 -> 64 rows each; also SMSP-pair phase
    const int warp_n = wid & 3;       // 0..3 -> 32 cols each
    const int cta    = blockIdx.x;

    const int ks_off = warp_m * 4;    // anti-phase the two warps per SMSP

    const int my_tiles = (NTILES - 1 - cta) / NSM + 1;
    const int total_gs = my_tiles * NSTG;

    if (tid == 0) {
        #pragma unroll
        for (int b = 0; b < NBUF; b++) {
            mbar_init(mbarF_u32 + b * 8, 1);
            mbar_init(mbarE_u32 + b * 8, 8);   // one arrive per warp
        }
    }
    __syncthreads();

    if (tid == 0) {
        issue_gs(smem_u32, mbarF_u32, 0, cta);
        issue_gs(smem_u32, mbarF_u32, 1, cta);
    }

    float acck[4][4][4], accm[4][4][4];
    #pragma unroll
    for (int mt = 0; mt < 4; mt++)
        #pragma unroll
        for (int nt = 0; nt < 4; nt++)
            #pragma unroll
            for (int q = 0; q < 4; q++) { acck[mt][nt][q] = 0.f; accm[mt][nt][q] = 0.f; }

    const int a_row = lane & 15;
    const int a_sel = lane >> 4;
    const int b_row = (lane & 7) + ((lane & 16) >> 1);
    const int b_sel = (lane & 8) ? 1 : 0;

    // Wait for stage 0 once; subsequent waits are hoisted into MMA shadows.
    mbar_wait(mbarF_u32, 0);

    for (int gs = 0; gs < total_gs; gs++) {
        const int b = gs & 1;

        const uint32_t sA  = smem_u32 + b * STAGE_BYTES;
        const uint32_t sBk = sA + 32768;
        const uint32_t sBm = sA + 65536;

        #pragma unroll
        for (int ksi = 0; ksi < 8; ksi++) {
            const int ks  = (ksi + ks_off) & 7;   // anti-phased traversal
            const int sub = (ks >> 2) * SUB_BYTES;
            const int kk  = ks & 3;
            uint32_t af[4][4];
            #pragma unroll
            for (int mt = 0; mt < 4; mt++) {
                int row = warp_m * 64 + mt * 16 + a_row;
                int ch  = (kk * 2 + a_sel) ^ (row & 7);
                ldmatrix_x4(af[mt], sA + sub + row * 128 + ch * 16);
            }
            uint32_t bk[4][2], bmu[4][2];
            #pragma unroll
            for (int bt = 0; bt < 2; bt++) {
                int row = warp_n * 32 + bt * 16 + b_row;
                int ch  = (kk * 2 + b_sel) ^ (row & 7);
                uint32_t r[4];
                ldmatrix_x4(r, sBk + sub + row * 128 + ch * 16);
                bk[2*bt  ][0] = r[0]; bk[2*bt  ][1] = r[1];
                bk[2*bt+1][0] = r[2]; bk[2*bt+1][1] = r[3];
                uint32_t t[4];
                ldmatrix_x4(t, sBm + sub + row * 128 + ch * 16);
                bmu[2*bt  ][0] = t[0]; bmu[2*bt  ][1] = t[1];
                bmu[2*bt+1][0] = t[2]; bmu[2*bt+1][1] = t[3];
            }

            if (ksi == 7) {
                // Early release: all smem reads of this stage are issued.
                if (lane == 0) mbar_arrive(mbarE_u32 + b * 8);
                // Hoisted wait for next stage: overlaps the final MMA batch.
                if (gs + 1 < total_gs) {
                    const int n = gs + 1;
                    mbar_wait(mbarF_u32 + (n & 1) * 8, (n >> 1) & 1);
                }
            }

            #pragma unroll
            for (int mt = 0; mt < 4; mt++) {
                #pragma unroll
                for (int nt = 0; nt < 4; nt++) {
                    mma16816(acck[mt][nt], af[mt], bk[nt]);
                    mma16816(accm[mt][nt], af[mt], bmu[nt]);
                }
            }
        }

        // Producer: refill buffer b with global stage gs+2 (may be next tile).
        if (tid == 0 && gs + 2 < total_gs) {
            const int t = gs + 2;
            mbar_wait(mbarE_u32 + b * 8, (((t >> 1) & 1) ^ 1));
            issue_gs(smem_u32, mbarF_u32, t, cta);
        }

        // Tile finished: fused epilogue (overlaps next tile's loads).
        if ((gs & 15) == 15) {
            const int tile = cta + (gs >> 4) * NSM;
            const int bm = (tile >> 4) * BM;
            const int bn = (tile & 15) * BN;

            #pragma unroll
            for (int mt = 0; mt < 4; mt++) {
                int r0 = bm + warp_m * 64 + mt * 16 + (lane >> 2);
                #pragma unroll
                for (int nt = 0; nt < 4; nt++) {
                    int c = bn + warp_n * 32 + nt * 8 + (lane & 3) * 2;
                    float2 g = __ldg((const float2*)(gate + c));

                    float s0 = acck[mt][nt][0] * INV_SQRT_D;
                    float s1 = acck[mt][nt][1] * INV_SQRT_D;
                    float m0 = accm[mt][nt][0] * fmaxf(s0 - g.x, 0.f);
                    float m1 = accm[mt][nt][1] * fmaxf(s1 - g.y, 0.f);
                    size_t o0 = (size_t)r0 * OUT_F + c;
                    *(float2*)(outScores + o0) = make_float2(s0, s1);
                    *(float2*)(outFinal  + o0) = make_float2(m0, m1);
                    *(float2*)(outMasked + o0) = make_float2(m0, m1);

                    float s2 = acck[mt][nt][2] * INV_SQRT_D;
                    float s3 = acck[mt][nt][3] * INV_SQRT_D;
                    float m2 = accm[mt][nt][2] * fmaxf(s2 - g.x, 0.f);
                    float m3 = accm[mt][nt][3] * fmaxf(s3 - g.y, 0.f);
                    size_t o1 = (size_t)(r0 + 8) * OUT_F + c;
                    *(float2*)(outScores + o1) = make_float2(s2, s3);
                    *(float2*)(outFinal  + o1) = make_float2(m2, m3);
                    *(float2*)(outMasked + o1) = make_float2(m2, m3);

                    #pragma unroll
                    for (int q = 0; q < 4; q++) { acck[mt][nt][q] = 0.f; accm[mt][nt][q] = 0.f; }
                }
            }
        }
    }
}

// ---------------------------------------------------------------------------
// Launch
// ---------------------------------------------------------------------------
extern "C" void kernel_launch(void* const* d_in, const int* in_sizes, int n_in,
                              void* d_out, int out_size) {
    const float* x     = (const float*)d_in[0];
    const float* mu    = (const float*)d_in[1];
    const float* sigma = (const float*)d_in[2];
    const float* gate  = (const float*)d_in[3];

    float* out  = (float*)d_out;
    float* out0 = out;                               // final_output
    float* out1 = out + (size_t)NROWS * OUT_F;       // scores
    float* out2 = out + 2 * (size_t)NROWS * OUT_F;   // masked_output

    prep_all<<<XBLOCKS + WBLOCKS, 256>>>(x, mu, sigma);

    cudaFuncSetAttribute(gemm_fused, cudaFuncAttributeMaxDynamicSharedMemorySize, SMEM_TOTAL);
    gemm_fused<<<NSM, NTHREADS, SMEM_TOTAL>>>(gate, out0, out1, out2);
}